// round 11
// baseline (speedup 1.0000x reference)
#include <cuda_runtime.h>
#include <cstdint>

#define N_NODES 50000
#define N_EDGES 1600000
#define IN_DIM 64
#define HD 64
#define NUM_HEADS 4
#define OUT_DIM 16
#define SCAN_BLK 196   // ceil(50000/256)

// ---------------- device scratch ----------------
__device__ float g_Q[N_NODES * HD];
__device__ float g_K[N_NODES * HD];
__device__ float g_V[N_NODES * HD];
__device__ float g_Z[N_NODES * NUM_HEADS];
__device__ int   g_cnt[N_NODES];
__device__ int   g_bsum[256];
__device__ int   g_perm[N_EDGES];
__device__ int   g_sdst[N_EDGES];
__device__ int   g_ssrc[N_EDGES];

// ---------------- helpers ----------------
__device__ __forceinline__ void red_add_v4(float* p, float a, float b, float c, float d) {
    asm volatile("red.global.add.v4.f32 [%0], {%1,%2,%3,%4};"
                 :: "l"(p), "f"(a), "f"(b), "f"(c), "f"(d) : "memory");
}
__device__ __forceinline__ uint32_t f2tf32(float f) {
    uint32_t r;
    asm("cvt.rna.tf32.f32 %0, %1;" : "=r"(r) : "f"(f));
    return r;
}
__device__ __forceinline__ void mma_tf32(float d[4], uint32_t a0, uint32_t a1,
                                         uint32_t a2, uint32_t a3,
                                         uint32_t b0, uint32_t b1) {
    asm("mma.sync.aligned.m16n8k8.row.col.f32.tf32.tf32.f32 "
        "{%0,%1,%2,%3}, {%4,%5,%6,%7}, {%8,%9}, {%0,%1,%2,%3};"
        : "+f"(d[0]), "+f"(d[1]), "+f"(d[2]), "+f"(d[3])
        : "r"(a0), "r"(a1), "r"(a2), "r"(a3), "r"(b0), "r"(b1));
}

// ---------------- zero init ----------------
__global__ void zero_kernel(float* __restrict__ out) {
    int i = blockIdx.x * blockDim.x + threadIdx.x;
    if (i < N_NODES * HD) out[i] = 0.0f;
    if (i < N_NODES * NUM_HEADS) g_Z[i] = 0.0f;
    if (i < N_NODES) g_cnt[i] = 0;
}

// ---------------- counting sort by dst ----------------
__global__ void count_kernel(const int* __restrict__ eidx) {
    int e = blockIdx.x * 256 + threadIdx.x;
    if (e < N_EDGES) atomicAdd(&g_cnt[eidx[N_EDGES + e]], 1);
}
__global__ void scan_a_kernel() {
    __shared__ int s[256];
    int i = blockIdx.x * 256 + threadIdx.x;
    int v = (i < N_NODES) ? g_cnt[i] : 0;
    s[threadIdx.x] = v;
    __syncthreads();
    #pragma unroll
    for (int d = 1; d < 256; d <<= 1) {
        int t = (threadIdx.x >= d) ? s[threadIdx.x - d] : 0;
        __syncthreads();
        s[threadIdx.x] += t;
        __syncthreads();
    }
    if (i < N_NODES) g_cnt[i] = s[threadIdx.x] - v;     // exclusive
    if (threadIdx.x == 255) g_bsum[blockIdx.x] = s[255];
}
__global__ void scan_b_kernel() {
    __shared__ int s[256];
    int v = (threadIdx.x < SCAN_BLK) ? g_bsum[threadIdx.x] : 0;
    s[threadIdx.x] = v;
    __syncthreads();
    #pragma unroll
    for (int d = 1; d < 256; d <<= 1) {
        int t = (threadIdx.x >= d) ? s[threadIdx.x - d] : 0;
        __syncthreads();
        s[threadIdx.x] += t;
        __syncthreads();
    }
    if (threadIdx.x < SCAN_BLK) g_bsum[threadIdx.x] = s[threadIdx.x] - v;  // exclusive
}
__global__ void scan_c_kernel() {
    int i = blockIdx.x * 256 + threadIdx.x;
    if (i < N_NODES) g_cnt[i] += g_bsum[blockIdx.x];
}
__global__ void scatter_kernel(const int* __restrict__ eidx) {
    int e = blockIdx.x * 256 + threadIdx.x;
    if (e < N_EDGES) {
        int dst = eidx[N_EDGES + e];
        int pos = atomicAdd(&g_cnt[dst], 1);
        g_perm[pos] = e;
        g_sdst[pos] = dst;
        g_ssrc[pos] = eidx[e];
    }
}

// ---------------- node projections (R3 scalar, known good) ----------------
#define PROJ_SMEM_FLOATS (128 * 65 + 64 * 64 + 64)
__global__ __launch_bounds__(128)
void proj_kernel(const float* __restrict__ x,
                 const float* __restrict__ WQ, const float* __restrict__ bQ,
                 const float* __restrict__ WK, const float* __restrict__ bK,
                 const float* __restrict__ WV, const float* __restrict__ bV) {
    const float* W; const float* b; float* out;
    if (blockIdx.y == 0)      { W = WQ; b = bQ; out = g_Q; }
    else if (blockIdx.y == 1) { W = WK; b = bK; out = g_K; }
    else                      { W = WV; b = bV; out = g_V; }

    extern __shared__ float sm[];
    float* x_s = sm;
    float* w_s = sm + 128 * 65;
    float* b_s = w_s + 64 * 64;

    const int tid = threadIdx.x;
    const int base = blockIdx.x * 128;

    {
        const float4* W4 = reinterpret_cast<const float4*>(W);
        float4* ws4 = reinterpret_cast<float4*>(w_s);
        #pragma unroll
        for (int i = tid; i < 1024; i += 128) ws4[i] = W4[i];
    }
    if (tid < 64) b_s[tid] = b[tid];

    for (int f = tid; f < 128 * 16; f += 128) {
        int r = f >> 4, q = f & 15;
        int gr = base + r;
        if (gr >= N_NODES) gr = N_NODES - 1;
        float4 v = reinterpret_cast<const float4*>(x + (size_t)gr * 64)[q];
        float* d = x_s + r * 65 + q * 4;
        d[0] = v.x; d[1] = v.y; d[2] = v.z; d[3] = v.w;
    }
    __syncthreads();

    const int eg = tid >> 3, dg = tid & 7;

    float acc[8][8];
    #pragma unroll
    for (int i = 0; i < 8; i++)
        #pragma unroll
        for (int j = 0; j < 8; j++) acc[i][j] = 0.0f;

    const float4* ws4 = reinterpret_cast<const float4*>(w_s);
    #pragma unroll 4
    for (int c = 0; c < 64; c++) {
        float4 w0 = ws4[c * 16 + dg * 2];
        float4 w1 = ws4[c * 16 + dg * 2 + 1];
        float a[8];
        #pragma unroll
        for (int i = 0; i < 8; i++) a[i] = x_s[(eg * 8 + i) * 65 + c];
        #pragma unroll
        for (int i = 0; i < 8; i++) {
            acc[i][0] += a[i] * w0.x; acc[i][1] += a[i] * w0.y;
            acc[i][2] += a[i] * w0.z; acc[i][3] += a[i] * w0.w;
            acc[i][4] += a[i] * w1.x; acc[i][5] += a[i] * w1.y;
            acc[i][6] += a[i] * w1.z; acc[i][7] += a[i] * w1.w;
        }
    }

    float bb[8];
    #pragma unroll
    for (int j = 0; j < 8; j++) bb[j] = b_s[dg * 8 + j];
    #pragma unroll
    for (int i = 0; i < 8; i++) {
        int n = base + eg * 8 + i;
        if (n < N_NODES) {
            float4 o0 = make_float4(acc[i][0] + bb[0], acc[i][1] + bb[1], acc[i][2] + bb[2], acc[i][3] + bb[3]);
            float4 o1 = make_float4(acc[i][4] + bb[4], acc[i][5] + bb[5], acc[i][6] + bb[6], acc[i][7] + bb[7]);
            float4* dst = reinterpret_cast<float4*>(out + (size_t)n * 64 + dg * 8);
            dst[0] = o0; dst[1] = o1;
        }
    }
}

// ---------------- fused edge kernel over dst-sorted edges ----------------
// Tile = 128 sorted edges. MMA per R8's verified mapping. Epilogue: thread =
// (run of 4 consecutive sorted edges, head); Q + accumulator held in registers
// across same-dst edges, RED flush only on dst change / run end.
#define TILE_E   128
#define EA_OFF   0               // 128 rows x stride 68 (tf32 in, fp32 E out)
#define EA_STR   68
#define W_OFF    (TILE_E * 68)   // 64 rows(k) x stride 72
#define W_STR    72
#define BIAS_OFF (W_OFF + 64 * 72)
#define PE_OFF   (BIAS_OFF + 64)          // 128 ints (perm)
#define SI_OFF   (PE_OFF + TILE_E)        // 128 ints
#define DI_OFF   (SI_OFF + TILE_E)        // 128 ints
#define EDGE_SMEM_FLOATS (DI_OFF + TILE_E)

__global__ __launch_bounds__(128, 4)
void edge_kernel(const float* __restrict__ ea,
                 const float* __restrict__ WE, const float* __restrict__ bE,
                 float* __restrict__ out) {
    extern __shared__ float sm[];
    uint32_t* ea_s = reinterpret_cast<uint32_t*>(sm + EA_OFF);
    float* E_s     = sm + EA_OFF;
    uint32_t* w_s  = reinterpret_cast<uint32_t*>(sm + W_OFF);
    float* bias_s  = sm + BIAS_OFF;
    int* pe_s      = reinterpret_cast<int*>(sm + PE_OFF);
    int* si_s      = reinterpret_cast<int*>(sm + SI_OFF);
    int* di_s      = reinterpret_cast<int*>(sm + DI_OFF);

    const int tid = threadIdx.x;
    const int base = blockIdx.x * TILE_E;

    if (tid < 64) bias_s[tid] = bE[tid];
    pe_s[tid] = g_perm[base + tid];
    si_s[tid] = g_ssrc[base + tid];
    di_s[tid] = g_sdst[base + tid];

    // stage B = WE (row-major [k][n]) as tf32 bits, stride 72
    for (int f = tid; f < 64 * 16; f += 128) {
        int k = f >> 4, q = f & 15;
        float4 v = reinterpret_cast<const float4*>(WE + (size_t)k * 64)[q];
        uint4 t;
        t.x = f2tf32(v.x); t.y = f2tf32(v.y); t.z = f2tf32(v.z); t.w = f2tf32(v.w);
        *reinterpret_cast<uint4*>(w_s + k * W_STR + q * 4) = t;
    }
    __syncthreads();   // perm ready for gather

    // stage A = gathered ea rows (tf32 bits), stride 68
    for (int f = tid; f < TILE_E * 16; f += 128) {
        int r = f >> 4, q = f & 15;
        int e = pe_s[r];
        float4 v = reinterpret_cast<const float4*>(ea + (size_t)e * 64)[q];
        uint4 t;
        t.x = f2tf32(v.x); t.y = f2tf32(v.y); t.z = f2tf32(v.z); t.w = f2tf32(v.w);
        *reinterpret_cast<uint4*>(ea_s + r * EA_STR + q * 4) = t;
    }
    __syncthreads();

    const int lane = tid & 31;
    const int warp = tid >> 5;
    const int g  = lane >> 2;
    const int tg = lane & 3;
    const int wrow = warp * 32;

    // ---- Phase A: E = ea @ WE via m16n8k8 tf32 mma (R8-verified) ----
    float acc[2][8][4];
    #pragma unroll
    for (int mt = 0; mt < 2; mt++)
        #pragma unroll
        for (int nt = 0; nt < 8; nt++)
            #pragma unroll
            for (int j = 0; j < 4; j++) acc[mt][nt][j] = 0.0f;

    #pragma unroll
    for (int k8 = 0; k8 < 8; k8++) {
        uint32_t a[2][4];
        #pragma unroll
        for (int mt = 0; mt < 2; mt++) {
            int r0 = wrow + mt * 16 + g;
            a[mt][0] = ea_s[(r0)     * EA_STR + k8 * 8 + tg];
            a[mt][1] = ea_s[(r0 + 8) * EA_STR + k8 * 8 + tg];
            a[mt][2] = ea_s[(r0)     * EA_STR + k8 * 8 + tg + 4];
            a[mt][3] = ea_s[(r0 + 8) * EA_STR + k8 * 8 + tg + 4];
        }
        #pragma unroll
        for (int nt = 0; nt < 8; nt++) {
            uint32_t b0 = w_s[(k8 * 8 + tg)     * W_STR + nt * 8 + g];
            uint32_t b1 = w_s[(k8 * 8 + tg + 4) * W_STR + nt * 8 + g];
            mma_tf32(acc[0][nt], a[0][0], a[0][1], a[0][2], a[0][3], b0, b1);
            mma_tf32(acc[1][nt], a[1][0], a[1][1], a[1][2], a[1][3], b0, b1);
        }
    }

    // store E (+bias) into this warp's own rows
    #pragma unroll
    for (int mt = 0; mt < 2; mt++) {
        #pragma unroll
        for (int rr = 0; rr < 2; rr++) {
            const int row = wrow + mt * 16 + rr * 8 + g;
            #pragma unroll
            for (int nt = 0; nt < 8; nt++) {
                const int c0 = nt * 8 + tg * 2;
                float2 bb = *reinterpret_cast<const float2*>(bias_s + c0);
                *reinterpret_cast<float2*>(E_s + row * EA_STR + c0) =
                    make_float2(acc[mt][nt][rr * 2 + 0] + bb.x,
                                acc[mt][nt][rr * 2 + 1] + bb.y);
            }
        }
    }
    __syncthreads();

    // ---- Phase B: segmented epilogue. thread = (run of 4 edges, head) ----
    const int run = tid >> 2;      // 0..31
    const int h   = tid & 3;       // head

    float4 Qr[4];
    float4 A[4];
    float zacc = 0.0f;
    int cur = -1;

    #pragma unroll
    for (int i = 0; i < 4; i++) {
        const int le  = run * 4 + i;
        const int dst = di_s[le];
        const int src = si_s[le];

        if (dst != cur) {
            if (cur >= 0) {
                float* ob = out + (size_t)cur * 64 + h * 16;
                red_add_v4(ob,      A[0].x, A[0].y, A[0].z, A[0].w);
                red_add_v4(ob + 4,  A[1].x, A[1].y, A[1].z, A[1].w);
                red_add_v4(ob + 8,  A[2].x, A[2].y, A[2].z, A[2].w);
                red_add_v4(ob + 12, A[3].x, A[3].y, A[3].z, A[3].w);
                atomicAdd(g_Z + (size_t)cur * 4 + h, zacc);
            }
            cur = dst;
            const float4* Qp = reinterpret_cast<const float4*>(g_Q + (size_t)dst * 64 + h * 16);
            #pragma unroll
            for (int q = 0; q < 4; q++) Qr[q] = Qp[q];
            #pragma unroll
            for (int q = 0; q < 4; q++) A[q] = make_float4(0.f, 0.f, 0.f, 0.f);
            zacc = 0.0f;
        }

        const float4* Kp = reinterpret_cast<const float4*>(g_K + (size_t)src * 64 + h * 16);
        const float4* Ep = reinterpret_cast<const float4*>(E_s + le * EA_STR + h * 16);
        float p = 0.0f;
        #pragma unroll
        for (int q = 0; q < 4; q++) {
            float4 k = Kp[q];
            float4 e = Ep[q];
            p += k.x * Qr[q].x * e.x + k.y * Qr[q].y * e.y
               + k.z * Qr[q].z * e.z + k.w * Qr[q].w * e.w;
        }
        float s = __expf(fminf(fmaxf(p * 0.25f, -5.0f), 5.0f));
        zacc += s;

        const float4* Vp = reinterpret_cast<const float4*>(g_V + (size_t)src * 64 + h * 16);
        #pragma unroll
        for (int q = 0; q < 4; q++) {
            float4 v = Vp[q];
            A[q].x += v.x * s; A[q].y += v.y * s; A[q].z += v.z * s; A[q].w += v.w * s;
        }
    }
    // final flush
    {
        float* ob = out + (size_t)cur * 64 + h * 16;
        red_add_v4(ob,      A[0].x, A[0].y, A[0].z, A[0].w);
        red_add_v4(ob + 4,  A[1].x, A[1].y, A[1].z, A[1].w);
        red_add_v4(ob + 8,  A[2].x, A[2].y, A[2].z, A[2].w);
        red_add_v4(ob + 12, A[3].x, A[3].y, A[3].z, A[3].w);
        atomicAdd(g_Z + (size_t)cur * 4 + h, zacc);
    }
}

// ---------------- finalize ----------------
__global__ void finalize_kernel(float* __restrict__ out) {
    int i = blockIdx.x * blockDim.x + threadIdx.x;
    if (i < N_NODES * HD) {
        int n = i >> 6;
        int h = (i >> 4) & 3;
        out[i] = out[i] / (g_Z[n * 4 + h] + 1e-6f);
    }
}

// ---------------- launch ----------------
extern "C" void kernel_launch(void* const* d_in, const int* in_sizes, int n_in,
                              void* d_out, int out_size) {
    const float* x   = (const float*)d_in[0];
    const float* ea  = (const float*)d_in[1];
    const int*   ei  = (const int*)  d_in[2];
    const float* WQ  = (const float*)d_in[3];
    const float* bQ  = (const float*)d_in[4];
    const float* WK  = (const float*)d_in[5];
    const float* bK  = (const float*)d_in[6];
    const float* WE  = (const float*)d_in[7];
    const float* bE  = (const float*)d_in[8];
    const float* WV  = (const float*)d_in[9];
    const float* bV  = (const float*)d_in[10];
    float* out = (float*)d_out;

    static_assert(EDGE_SMEM_FLOATS * 4 * 4 < 228 * 1024, "smem occupancy");
    cudaFuncSetAttribute(edge_kernel, cudaFuncAttributeMaxDynamicSharedMemorySize,
                         EDGE_SMEM_FLOATS * (int)sizeof(float));
    cudaFuncSetAttribute(proj_kernel, cudaFuncAttributeMaxDynamicSharedMemorySize,
                         PROJ_SMEM_FLOATS * (int)sizeof(float));

    // zero + projections
    zero_kernel<<<(N_NODES * HD + 255) / 256, 256>>>(out);
    {
        dim3 grid((N_NODES + 127) / 128, 3);
        proj_kernel<<<grid, 128, PROJ_SMEM_FLOATS * sizeof(float)>>>(x, WQ, bQ, WK, bK, WV, bV);
    }
    // counting sort by dst
    count_kernel<<<(N_EDGES + 255) / 256, 256>>>(ei);
    scan_a_kernel<<<SCAN_BLK, 256>>>();
    scan_b_kernel<<<1, 256>>>();
    scan_c_kernel<<<SCAN_BLK, 256>>>();
    scatter_kernel<<<(N_EDGES + 255) / 256, 256>>>(ei);
    // fused edge GEMM + attention over sorted edges
    edge_kernel<<<N_EDGES / TILE_E, 128, EDGE_SMEM_FLOATS * sizeof(float)>>>(ea, WE, bE, out);
    // finalize
    finalize_kernel<<<(N_NODES * HD + 255) / 256, 256>>>(out);
}